// round 3
// baseline (speedup 1.0000x reference)
#include <cuda_runtime.h>

// out[:, :DIM]  = p + a * tanh(q) ; out[:, DIM:] = q
// p = pq[:, :DIM], q = pq[:, DIM:], DIM = 2048, rows = 16384.
//
// R2: 4 float4-pairs per thread, all loads front-batched (MLP=8 independent
// LDGs) to keep the L1tex wavefront queue full; streaming cache hints
// (__ldcs/__stcs) since the 512MiB stream has zero reuse and should not
// thrash L2. Grid stride is a multiple of HALF4, so all 4 items of a thread
// share the same column -> one `a` load, index math is adds only.

template <int HALF4, int ITEMS>
__global__ __launch_bounds__(256)
void fused_tanh_kernel(const float4* __restrict__ pq,
                       const float4* __restrict__ a,
                       float4* __restrict__ out,
                       int stride_pairs) {
    int tid = blockIdx.x * blockDim.x + threadIdx.x;

    int c    = tid & (HALF4 - 1);        // same column for all ITEMS
    int row0 = tid / HALF4;
    int drow = stride_pairs / HALF4;     // rows advanced per item

    float4 p[ITEMS], q[ITEMS];
    long base[ITEMS];

    // Front-batch all 2*ITEMS independent loads.
    #pragma unroll
    for (int k = 0; k < ITEMS; k++) {
        long row = row0 + (long)k * drow;
        base[k] = row * (2 * HALF4) + c;
        p[k] = __ldcs(&pq[base[k]]);
        q[k] = __ldcs(&pq[base[k] + HALF4]);
    }

    float4 av = __ldg(&a[c]);

    #pragma unroll
    for (int k = 0; k < ITEMS; k++) {
        float4 r;
        r.x = fmaf(av.x, tanhf(q[k].x), p[k].x);
        r.y = fmaf(av.y, tanhf(q[k].y), p[k].y);
        r.z = fmaf(av.z, tanhf(q[k].z), p[k].z);
        r.w = fmaf(av.w, tanhf(q[k].w), p[k].w);
        __stcs(&out[base[k]], r);
        __stcs(&out[base[k] + HALF4], q[k]);
    }
}

// Generic fallback (any shape), one pair per thread.
__global__ __launch_bounds__(256)
void fused_tanh_kernel_generic(const float4* __restrict__ pq,
                               const float4* __restrict__ a,
                               float4* __restrict__ out,
                               int n_pairs, int half4) {
    int i = blockIdx.x * blockDim.x + threadIdx.x;
    if (i >= n_pairs) return;
    int row = i / half4;
    int c   = i - row * half4;
    long base = (long)row * (2 * half4) + c;

    float4 p  = pq[base];
    float4 q  = pq[base + half4];
    float4 av = __ldg(&a[c]);

    float4 r;
    r.x = fmaf(av.x, tanhf(q.x), p.x);
    r.y = fmaf(av.y, tanhf(q.y), p.y);
    r.z = fmaf(av.z, tanhf(q.z), p.z);
    r.w = fmaf(av.w, tanhf(q.w), p.w);

    out[base]         = r;
    out[base + half4] = q;
}

extern "C" void kernel_launch(void* const* d_in, const int* in_sizes, int n_in,
                              void* d_out, int out_size) {
    const float4* pq  = (const float4*)d_in[0];
    const float4* a   = (const float4*)d_in[1];
    float4*       out = (float4*)d_out;

    int dim     = in_sizes[1];            // 2048
    int total   = in_sizes[0];            // rows * 2*dim
    int rows    = total / (2 * dim);      // 16384
    int half4   = dim / 4;                // 512
    int n_pairs = rows * half4;           // 8,388,608

    constexpr int ITEMS   = 4;
    constexpr int THREADS = 256;

    // Fast path: DIM=2048, n_pairs divisible by THREADS*ITEMS, and the
    // resulting stride is a multiple of half4 (so column is invariant per
    // thread and no bounds checks are needed).
    if (half4 == 512 && n_pairs % (THREADS * ITEMS) == 0 &&
        (n_pairs / ITEMS) % half4 == 0) {
        int blocks = n_pairs / (THREADS * ITEMS);   // 8192
        int stride = blocks * THREADS;              // 2,097,152 (mult of 512)
        fused_tanh_kernel<512, ITEMS><<<blocks, THREADS>>>(pq, a, out, stride);
    } else {
        int blocks = (n_pairs + THREADS - 1) / THREADS;
        fused_tanh_kernel_generic<<<blocks, THREADS>>>(pq, a, out, n_pairs, half4);
    }
}

// round 4
// speedup vs baseline: 1.0382x; 1.0382x over previous
#include <cuda_runtime.h>

// out[:, :DIM]  = p + a * tanh(q) ; out[:, DIM:] = q
// p = pq[:, :DIM], q = pq[:, DIM:], DIM = 2048, rows = 16384.
//
// R3: back to the R1 shape (one float4-pair per thread, 32 regs, high occ —
// R2 proved per-thread batching kills occupancy and regresses). Single change
// vs R1: streaming cache hints (__ldcs / __stcs) on the 512MiB zero-reuse
// stream to stop L2 thrash.

template <int HALF4>  // float4s per half-row (DIM/4), power of two
__global__ __launch_bounds__(256)
void fused_tanh_kernel(const float4* __restrict__ pq,
                       const float4* __restrict__ a,
                       float4* __restrict__ out,
                       unsigned n_pairs) {
    unsigned i = blockIdx.x * blockDim.x + threadIdx.x;
    if (i >= n_pairs) return;

    unsigned c   = i & (HALF4 - 1);
    unsigned row = i / HALF4;
    size_t base  = (size_t)row * (2 * HALF4) + c;

    float4 p  = __ldcs(&pq[base]);
    float4 q  = __ldcs(&pq[base + HALF4]);
    float4 av = __ldg(&a[c]);

    float4 r;
    r.x = fmaf(av.x, tanhf(q.x), p.x);
    r.y = fmaf(av.y, tanhf(q.y), p.y);
    r.z = fmaf(av.z, tanhf(q.z), p.z);
    r.w = fmaf(av.w, tanhf(q.w), p.w);

    __stcs(&out[base], r);
    __stcs(&out[base + HALF4], q);
}

// Generic fallback (runtime half4) for unexpected shapes.
__global__ __launch_bounds__(256)
void fused_tanh_kernel_generic(const float4* __restrict__ pq,
                               const float4* __restrict__ a,
                               float4* __restrict__ out,
                               unsigned n_pairs, int half4) {
    unsigned i = blockIdx.x * blockDim.x + threadIdx.x;
    if (i >= n_pairs) return;
    unsigned row = i / half4;
    unsigned c   = i - row * half4;
    size_t base  = (size_t)row * (2 * half4) + c;

    float4 p  = pq[base];
    float4 q  = pq[base + half4];
    float4 av = __ldg(&a[c]);

    float4 r;
    r.x = fmaf(av.x, tanhf(q.x), p.x);
    r.y = fmaf(av.y, tanhf(q.y), p.y);
    r.z = fmaf(av.z, tanhf(q.z), p.z);
    r.w = fmaf(av.w, tanhf(q.w), p.w);

    out[base]         = r;
    out[base + half4] = q;
}

extern "C" void kernel_launch(void* const* d_in, const int* in_sizes, int n_in,
                              void* d_out, int out_size) {
    const float4* pq  = (const float4*)d_in[0];
    const float4* a   = (const float4*)d_in[1];
    float4*       out = (float4*)d_out;

    int dim      = in_sizes[1];            // 2048
    int total    = in_sizes[0];            // rows * 2*dim
    int rows     = total / (2 * dim);      // 16384
    int half4    = dim / 4;                // 512
    unsigned n_pairs = (unsigned)rows * half4;  // 8,388,608

    constexpr int THREADS = 256;
    unsigned blocks = (n_pairs + THREADS - 1) / THREADS;

    if (half4 == 512) {
        fused_tanh_kernel<512><<<blocks, THREADS>>>(pq, a, out, n_pairs);
    } else {
        fused_tanh_kernel_generic<<<blocks, THREADS>>>(pq, a, out, n_pairs, half4);
    }
}